// round 11
// baseline (speedup 1.0000x reference)
#include <cuda_runtime.h>
#include <cuda_bf16.h>

// Output = C_total * conv3x3(inp, k): the 1000-step LIF recurrence is linear for
// I in [0,9) (spike/reset clamps provably inactive), so it collapses to a scalar.
//
// R10: R9 (batch-2 rows, 2-col threads, 32 regs, single wave — best kernel time
// 21.25us) + streaming cache policy on BOTH streams (__ldcs / __stcs). Input and
// output have ~zero L2 reuse; evict-first keeps them from fighting for L2 and
// smooths DRAM writeback. Zero register / structural risk.

#define TW   256   // threads per block (each handles 2 output columns)
#define ROWS 32    // output rows per block; strips = 16, grid = 1024 = 1 wave

struct Row { float2 lo, hi; };   // input cols x0..x0+3 for this thread

__device__ __forceinline__ Row load_row(const float* p)
{
    Row r;
    r.lo = __ldcs((const float2*)p);        // evict-first: no reuse after this read
    r.hi = __ldcs((const float2*)(p + 2));
    return r;
}

__global__ __launch_bounds__(TW, 7)
void snn_conv_kernel(const float* __restrict__ inp,
                     const float* __restrict__ kw,
                     float* __restrict__ out,
                     float cscale)
{
    const int W  = 512;
    const int OW = 510;

    const int n  = blockIdx.y;
    const int y0 = blockIdx.x * ROWS;        // 0,32,...,480
    const int t  = threadIdx.x;

    const bool valid = (2 * t) <= 508;       // thread 255 computes garbage, no store
    const int  x0    = valid ? 2 * t : 508;  // clamp keeps all loads in-bounds

    // 3x3 weights with the LIF scalar folded in
    const float k00 = kw[0]*cscale, k01 = kw[1]*cscale, k02 = kw[2]*cscale;
    const float k10 = kw[3]*cscale, k11 = kw[4]*cscale, k12 = kw[5]*cscale;
    const float k20 = kw[6]*cscale, k21 = kw[7]*cscale, k22 = kw[8]*cscale;

    const float* pin = inp + (size_t)n * W * W + (size_t)y0 * W + x0;
    float*       po  = out + (size_t)n * OW * OW + (size_t)y0 * OW + x0;

    // Window: A=row y, B=row y+1 (persistent); C,D loaded per pair-iteration.
    Row A = load_row(pin);
    Row B = load_row(pin + W);
    pin += 2 * W;                            // points at row y0+2

#pragma unroll
    for (int p = 0; p < ROWS / 2; p++) {
        const int y = y0 + 2 * p;
        if (y >= 510) break;                 // only strip 15, p=15 (before any load)

        // Issue BOTH row loads up front: 4 independent LDG.64 in flight
        Row C = load_row(pin);
        Row D = load_row(pin + W);
        pin += 2 * W;

        // out(y): rows A,B,C   |   out(y+1): rows B,C,D
        float s0 = k00*A.lo.x + k01*A.lo.y + k02*A.hi.x
                 + k10*B.lo.x + k11*B.lo.y + k12*B.hi.x
                 + k20*C.lo.x + k21*C.lo.y + k22*C.hi.x;
        float s1 = k00*A.lo.y + k01*A.hi.x + k02*A.hi.y
                 + k10*B.lo.y + k11*B.hi.x + k12*B.hi.y
                 + k20*C.lo.y + k21*C.hi.x + k22*C.hi.y;
        float u0 = k00*B.lo.x + k01*B.lo.y + k02*B.hi.x
                 + k10*C.lo.x + k11*C.lo.y + k12*C.hi.x
                 + k20*D.lo.x + k21*D.lo.y + k22*D.hi.x;
        float u1 = k00*B.lo.y + k01*B.hi.x + k02*B.hi.y
                 + k10*C.lo.y + k11*C.hi.x + k12*C.hi.y
                 + k20*D.lo.y + k21*D.hi.x + k22*D.hi.y;

        if (valid) {
            // x0 even, OW even -> 8B-aligned float2 streaming stores
            __stcs((float2*)(po),      make_float2(s0, s1));
            __stcs((float2*)(po + OW), make_float2(u0, u1));
        }
        po += 2 * OW;

        A = C;
        B = D;
    }
}

extern "C" void kernel_launch(void* const* d_in, const int* in_sizes, int n_in,
                              void* d_out, int out_size)
{
    const float* inp = (const float*)d_in[0];   // (64,512,512,1) fp32
    const float* k   = (const float*)d_in[1];   // (3,3,1,1) fp32
    float* out = (float*)d_out;                 // (64,510,510,1) fp32

    // Closed-form LIF coefficient (double precision, host, once per capture).
    const double DT = 0.01, R = 3000.0, C = 10.0, NS = 1000.0;
    double v  = (R * 1.0) / (R * C) * DT;   // v0 = 1e-3
    double vt = v;
    for (int i = 0; i < 999; i++) {
        v  = v + (-v + R * 1.0) / (R * C) * DT;
        vt = (v + vt) / NS;
    }
    const float cscale = (float)vt;         // ~1.0008e-3

    dim3 block(TW);
    dim3 grid((510 + ROWS - 1) / ROWS, 64); // 16 x 64 = 1024 blocks, single wave
    snn_conv_kernel<<<grid, block>>>(inp, k, out, cscale);
}

// round 13
// speedup vs baseline: 1.1820x; 1.1820x over previous
#include <cuda_runtime.h>
#include <cuda_bf16.h>

// Output = C_total * conv3x3(inp, k): the 1000-step LIF recurrence is linear for
// I in [0,9) (spike/reset clamps provably inactive), so it collapses to a scalar.
//
// R11: R9 (best kernel time, 21.25us: batch-2 rows, 2-col threads, 32 regs,
// 1024 blocks = single wave) with streaming policy on STORES ONLY. R10 showed
// __ldcs costs the inter-strip halo its L2 hits (loads stay default); __stcs is
// safe because output lines are never re-read.

#define TW   256   // threads per block (each handles 2 output columns)
#define ROWS 32    // output rows per block; strips = 16, grid = 1024 = 1 wave

struct Row { float2 lo, hi; };   // input cols x0..x0+3 for this thread

__device__ __forceinline__ Row load_row(const float* p)
{
    Row r;
    r.lo = *(const float2*)p;               // default policy: halo rows hit L2
    r.hi = *(const float2*)(p + 2);
    return r;
}

__global__ __launch_bounds__(TW, 7)
void snn_conv_kernel(const float* __restrict__ inp,
                     const float* __restrict__ kw,
                     float* __restrict__ out,
                     float cscale)
{
    const int W  = 512;
    const int OW = 510;

    const int n  = blockIdx.y;
    const int y0 = blockIdx.x * ROWS;        // 0,32,...,480
    const int t  = threadIdx.x;

    const bool valid = (2 * t) <= 508;       // thread 255 computes garbage, no store
    const int  x0    = valid ? 2 * t : 508;  // clamp keeps all loads in-bounds

    // 3x3 weights with the LIF scalar folded in
    const float k00 = kw[0]*cscale, k01 = kw[1]*cscale, k02 = kw[2]*cscale;
    const float k10 = kw[3]*cscale, k11 = kw[4]*cscale, k12 = kw[5]*cscale;
    const float k20 = kw[6]*cscale, k21 = kw[7]*cscale, k22 = kw[8]*cscale;

    const float* pin = inp + (size_t)n * W * W + (size_t)y0 * W + x0;
    float*       po  = out + (size_t)n * OW * OW + (size_t)y0 * OW + x0;

    // Window: A=row y, B=row y+1 (persistent); C,D loaded per pair-iteration.
    Row A = load_row(pin);
    Row B = load_row(pin + W);
    pin += 2 * W;                            // points at row y0+2

#pragma unroll
    for (int p = 0; p < ROWS / 2; p++) {
        const int y = y0 + 2 * p;
        if (y >= 510) break;                 // only strip 15, p=15 (before any load)

        // Issue BOTH row loads up front: 4 independent LDG.64 in flight
        Row C = load_row(pin);
        Row D = load_row(pin + W);
        pin += 2 * W;

        // out(y): rows A,B,C   |   out(y+1): rows B,C,D
        float s0 = k00*A.lo.x + k01*A.lo.y + k02*A.hi.x
                 + k10*B.lo.x + k11*B.lo.y + k12*B.hi.x
                 + k20*C.lo.x + k21*C.lo.y + k22*C.hi.x;
        float s1 = k00*A.lo.y + k01*A.hi.x + k02*A.hi.y
                 + k10*B.lo.y + k11*B.hi.x + k12*B.hi.y
                 + k20*C.lo.y + k21*C.hi.x + k22*C.hi.y;
        float u0 = k00*B.lo.x + k01*B.lo.y + k02*B.hi.x
                 + k10*C.lo.x + k11*C.lo.y + k12*C.hi.x
                 + k20*D.lo.x + k21*D.lo.y + k22*D.hi.x;
        float u1 = k00*B.lo.y + k01*B.hi.x + k02*B.hi.y
                 + k10*C.lo.y + k11*C.hi.x + k12*C.hi.y
                 + k20*D.lo.y + k21*D.hi.x + k22*D.hi.y;

        if (valid) {
            // x0 even, OW even -> 8B-aligned float2 streaming stores
            __stcs((float2*)(po),      make_float2(s0, s1));
            __stcs((float2*)(po + OW), make_float2(u0, u1));
        }
        po += 2 * OW;

        A = C;
        B = D;
    }
}

extern "C" void kernel_launch(void* const* d_in, const int* in_sizes, int n_in,
                              void* d_out, int out_size)
{
    const float* inp = (const float*)d_in[0];   // (64,512,512,1) fp32
    const float* k   = (const float*)d_in[1];   // (3,3,1,1) fp32
    float* out = (float*)d_out;                 // (64,510,510,1) fp32

    // Closed-form LIF coefficient (double precision, host, once per capture).
    const double DT = 0.01, R = 3000.0, C = 10.0, NS = 1000.0;
    double v  = (R * 1.0) / (R * C) * DT;   // v0 = 1e-3
    double vt = v;
    for (int i = 0; i < 999; i++) {
        v  = v + (-v + R * 1.0) / (R * C) * DT;
        vt = (v + vt) / NS;
    }
    const float cscale = (float)vt;         // ~1.0008e-3

    dim3 block(TW);
    dim3 grid((510 + ROWS - 1) / ROWS, 64); // 16 x 64 = 1024 blocks, single wave
    snn_conv_kernel<<<grid, block>>>(inp, k, out, cscale);
}

// round 14
// speedup vs baseline: 1.1926x; 1.0089x over previous
#include <cuda_runtime.h>
#include <cuda_bf16.h>

// Output = C_total * conv3x3(inp, k): the 1000-step LIF recurrence is linear for
// I in [0,9) (spike/reset clamps provably inactive), so it collapses to a scalar.
//
// R13: R11 body (batch-2 rows, 2-col threads, 32 regs, __stcs stores — kernel
// 20.96us) with each row-strip split in two along x: 128-thread blocks, 2048
// total -> 13.8 blocks/SM vs a 16-block cap at 32 regs -> ~87% occupancy,
// still strictly one wave (R11 was grid-quantized at 6.9/SM, occ 77%).
// No launch-bounds pin (R7 showed pinning regressions); reg creep to 36 still
// leaves cap 14 > 13.8, so the single-wave property is robust.

#define TW    128   // threads per block (each handles 2 output columns)
#define ROWS  32    // output rows per strip; 16 strips cover 510 rows
#define XCOLS 256   // output columns per block (2 x-blocks per strip)

struct Row { float2 lo, hi; };   // input cols x0..x0+3 for this thread

__device__ __forceinline__ Row load_row(const float* p)
{
    Row r;
    r.lo = *(const float2*)p;               // default policy: halo rows hit L2
    r.hi = *(const float2*)(p + 2);
    return r;
}

__global__ __launch_bounds__(TW)
void snn_conv_kernel(const float* __restrict__ inp,
                     const float* __restrict__ kw,
                     float* __restrict__ out,
                     float cscale)
{
    const int W  = 512;
    const int OW = 510;

    const int n  = blockIdx.y;
    const int y0 = (blockIdx.x >> 1) * ROWS;     // 0,32,...,480
    const int xb = (blockIdx.x & 1) * XCOLS;     // 0 or 256
    const int t  = threadIdx.x;

    const int  xt    = xb + 2 * t;           // nominal first output column
    const bool valid = xt <= 508;            // last thread of xb=256 is clamped
    const int  x0    = valid ? xt : 508;     // keeps all loads within cols 0..511

    // 3x3 weights with the LIF scalar folded in
    const float k00 = kw[0]*cscale, k01 = kw[1]*cscale, k02 = kw[2]*cscale;
    const float k10 = kw[3]*cscale, k11 = kw[4]*cscale, k12 = kw[5]*cscale;
    const float k20 = kw[6]*cscale, k21 = kw[7]*cscale, k22 = kw[8]*cscale;

    const float* pin = inp + (size_t)n * W * W + (size_t)y0 * W + x0;
    float*       po  = out + (size_t)n * OW * OW + (size_t)y0 * OW + x0;

    // Window: A=row y, B=row y+1 (persistent); C,D loaded per pair-iteration.
    Row A = load_row(pin);
    Row B = load_row(pin + W);
    pin += 2 * W;                            // points at row y0+2

#pragma unroll
    for (int p = 0; p < ROWS / 2; p++) {
        const int y = y0 + 2 * p;
        if (y >= 510) break;                 // only strip 15, p=15 (before any load)

        // Issue BOTH row loads up front: 4 independent LDG.64 in flight
        Row C = load_row(pin);
        Row D = load_row(pin + W);
        pin += 2 * W;

        // out(y): rows A,B,C   |   out(y+1): rows B,C,D
        float s0 = k00*A.lo.x + k01*A.lo.y + k02*A.hi.x
                 + k10*B.lo.x + k11*B.lo.y + k12*B.hi.x
                 + k20*C.lo.x + k21*C.lo.y + k22*C.hi.x;
        float s1 = k00*A.lo.y + k01*A.hi.x + k02*A.hi.y
                 + k10*B.lo.y + k11*B.hi.x + k12*B.hi.y
                 + k20*C.lo.y + k21*C.hi.x + k22*C.hi.y;
        float u0 = k00*B.lo.x + k01*B.lo.y + k02*B.hi.x
                 + k10*C.lo.x + k11*C.lo.y + k12*C.hi.x
                 + k20*D.lo.x + k21*D.lo.y + k22*D.hi.x;
        float u1 = k00*B.lo.y + k01*B.hi.x + k02*B.hi.y
                 + k10*C.lo.y + k11*C.hi.x + k12*C.hi.y
                 + k20*D.lo.y + k21*D.hi.x + k22*D.hi.y;

        if (valid) {
            // x0 even, OW even -> 8B-aligned float2 streaming stores;
            // output lines are never re-read, so evict-first is free L2 space
            __stcs((float2*)(po),      make_float2(s0, s1));
            __stcs((float2*)(po + OW), make_float2(u0, u1));
        }
        po += 2 * OW;

        A = C;
        B = D;
    }
}

extern "C" void kernel_launch(void* const* d_in, const int* in_sizes, int n_in,
                              void* d_out, int out_size)
{
    const float* inp = (const float*)d_in[0];   // (64,512,512,1) fp32
    const float* k   = (const float*)d_in[1];   // (3,3,1,1) fp32
    float* out = (float*)d_out;                 // (64,510,510,1) fp32

    // Closed-form LIF coefficient (double precision, host, once per capture).
    const double DT = 0.01, R = 3000.0, C = 10.0, NS = 1000.0;
    double v  = (R * 1.0) / (R * C) * DT;   // v0 = 1e-3
    double vt = v;
    for (int i = 0; i < 999; i++) {
        v  = v + (-v + R * 1.0) / (R * C) * DT;
        vt = (v + vt) / NS;
    }
    const float cscale = (float)vt;         // ~1.0008e-3

    dim3 block(TW);
    dim3 grid(2 * ((510 + ROWS - 1) / ROWS), 64);  // 32 x 64 = 2048 blocks, 1 wave
    snn_conv_kernel<<<grid, block>>>(inp, k, out, cscale);
}

// round 15
// speedup vs baseline: 1.2174x; 1.0208x over previous
#include <cuda_runtime.h>
#include <cuda_bf16.h>

// Output = C_total * conv3x3(inp, k): the 1000-step LIF recurrence is linear for
// I in [0,9) (spike/reset clamps provably inactive), so it collapses to a scalar.
//
// R14: champion config R11 (256-thr blocks, 2-col threads, batch-2 rows, 32
// regs, 1024 blocks single wave, __stcs stores — best kernel 20.96us), with the
// in-loop tail branch removed: the last strip's y0 clamps to 478, so strips 14
// and 15 overlap by 2 rows and every block runs exactly 16 uniform pair-
// iterations (overlapping blocks write identical values; deterministic).
// R13 established achieved occ is pinned ~77% regardless of geometry, so this
// geometry (the measured kernel-time minimum) is final.

#define TW   256   // threads per block (each handles 2 output columns)
#define ROWS 32    // output rows per block

struct Row { float2 lo, hi; };   // input cols x0..x0+3 for this thread

__device__ __forceinline__ Row load_row(const float* p)
{
    Row r;
    r.lo = *(const float2*)p;               // default policy: halo rows hit L2
    r.hi = *(const float2*)(p + 2);
    return r;
}

__global__ __launch_bounds__(TW, 7)
void snn_conv_kernel(const float* __restrict__ inp,
                     const float* __restrict__ kw,
                     float* __restrict__ out,
                     float cscale)
{
    const int W  = 512;
    const int OW = 510;

    const int n  = blockIdx.y;
    int y0 = blockIdx.x * ROWS;              // 0,32,...,480
    if (y0 > 478) y0 = 478;                  // last strip overlaps by 2 rows:
                                             // all blocks run full 16 pair-iters
    const int t  = threadIdx.x;

    const bool valid = (2 * t) <= 508;       // thread 255 computes garbage, no store
    const int  x0    = valid ? 2 * t : 508;  // clamp keeps all loads in-bounds

    // 3x3 weights with the LIF scalar folded in
    const float k00 = kw[0]*cscale, k01 = kw[1]*cscale, k02 = kw[2]*cscale;
    const float k10 = kw[3]*cscale, k11 = kw[4]*cscale, k12 = kw[5]*cscale;
    const float k20 = kw[6]*cscale, k21 = kw[7]*cscale, k22 = kw[8]*cscale;

    const float* pin = inp + (size_t)n * W * W + (size_t)y0 * W + x0;
    float*       po  = out + (size_t)n * OW * OW + (size_t)y0 * OW + x0;

    // Window: A=row y, B=row y+1 (persistent); C,D loaded per pair-iteration.
    Row A = load_row(pin);
    Row B = load_row(pin + W);
    pin += 2 * W;                            // points at row y0+2

#pragma unroll
    for (int p = 0; p < ROWS / 2; p++) {
        // Issue BOTH row loads up front: 4 independent LDG.64 in flight
        Row C = load_row(pin);
        Row D = load_row(pin + W);
        pin += 2 * W;

        // out(y): rows A,B,C   |   out(y+1): rows B,C,D
        float s0 = k00*A.lo.x + k01*A.lo.y + k02*A.hi.x
                 + k10*B.lo.x + k11*B.lo.y + k12*B.hi.x
                 + k20*C.lo.x + k21*C.lo.y + k22*C.hi.x;
        float s1 = k00*A.lo.y + k01*A.hi.x + k02*A.hi.y
                 + k10*B.lo.y + k11*B.hi.x + k12*B.hi.y
                 + k20*C.lo.y + k21*C.hi.x + k22*C.hi.y;
        float u0 = k00*B.lo.x + k01*B.lo.y + k02*B.hi.x
                 + k10*C.lo.x + k11*C.lo.y + k12*C.hi.x
                 + k20*D.lo.x + k21*D.lo.y + k22*D.hi.x;
        float u1 = k00*B.lo.y + k01*B.hi.x + k02*B.hi.y
                 + k10*C.lo.y + k11*C.hi.x + k12*C.hi.y
                 + k20*D.lo.y + k21*D.hi.x + k22*D.hi.y;

        if (valid) {
            // x0 even, OW even -> 8B-aligned float2 streaming stores;
            // output lines are never re-read, so evict-first is free L2 space
            __stcs((float2*)(po),      make_float2(s0, s1));
            __stcs((float2*)(po + OW), make_float2(u0, u1));
        }
        po += 2 * OW;

        A = C;
        B = D;
    }
}

extern "C" void kernel_launch(void* const* d_in, const int* in_sizes, int n_in,
                              void* d_out, int out_size)
{
    const float* inp = (const float*)d_in[0];   // (64,512,512,1) fp32
    const float* k   = (const float*)d_in[1];   // (3,3,1,1) fp32
    float* out = (float*)d_out;                 // (64,510,510,1) fp32

    // Closed-form LIF coefficient (double precision, host, once per capture).
    const double DT = 0.01, R = 3000.0, C = 10.0, NS = 1000.0;
    double v  = (R * 1.0) / (R * C) * DT;   // v0 = 1e-3
    double vt = v;
    for (int i = 0; i < 999; i++) {
        v  = v + (-v + R * 1.0) / (R * C) * DT;
        vt = (v + vt) / NS;
    }
    const float cscale = (float)vt;         // ~1.0008e-3

    dim3 block(TW);
    dim3 grid((510 + ROWS - 1) / ROWS, 64); // 16 x 64 = 1024 blocks, single wave
    snn_conv_kernel<<<grid, block>>>(inp, k, out, cscale);
}